// round 10
// baseline (speedup 1.0000x reference)
#include <cuda_runtime.h>

// S2Conv v5: no-smem streaming conv (L1-cached row reuse), recompute strategy.
// Pass A = conv + per-channel stats (no store). Finalize. Pass B = conv again
// + scale/bias + relu + store. N=64, C=128, T=2048, S=9.

#define Nn 64
#define Cc 128
#define Tt 2048
#define Ss 9
#define CG 32          // output channels per block (8 warps x 4)
#define TBLK 128       // t per block (32 lanes x 4)

__device__ float g_sum[Cc];
__device__ float g_sumsq[Cc];
__device__ float g_scale[Cc];
__device__ float g_bias[Cc];
__constant__ float c_w[Cc * Ss];

__global__ void init_kernel() {
    int i = threadIdx.x;
    if (i < Cc) { g_sum[i] = 0.0f; g_sumsq[i] = 0.0f; }
}

// Core conv for one thread: 4 channels (cb..cb+3) x 4 t (tb..tb+3).
// Streamed taps: row r (input channel cb-4+r) feeds acc[cl], cl in [r-8,r]&[0,3].
template<bool EDGE>
__device__ __forceinline__ void conv_quad(
    const float* __restrict__ xn, int cb, int tb, float4 (&acc)[4])
{
    #pragma unroll
    for (int r = 0; r < 12; r++) {
        const int cc = cb - 4 + r;
        if ((unsigned)cc < (unsigned)Cc) {          // warp-uniform branch
            const int off = 4 - (cc % 9);
            const float* xr = xn + (size_t)cc * Tt;
            const int t0 = tb + off;
            float4 tp;
            if (EDGE) {
                tp.x = ((unsigned)(t0 + 0) < (unsigned)Tt) ? __ldg(&xr[t0 + 0]) : 0.f;
                tp.y = ((unsigned)(t0 + 1) < (unsigned)Tt) ? __ldg(&xr[t0 + 1]) : 0.f;
                tp.z = ((unsigned)(t0 + 2) < (unsigned)Tt) ? __ldg(&xr[t0 + 2]) : 0.f;
                tp.w = ((unsigned)(t0 + 3) < (unsigned)Tt) ? __ldg(&xr[t0 + 3]) : 0.f;
            } else {
                tp.x = __ldg(&xr[t0 + 0]);
                tp.y = __ldg(&xr[t0 + 1]);
                tp.z = __ldg(&xr[t0 + 2]);
                tp.w = __ldg(&xr[t0 + 3]);
            }
            #pragma unroll
            for (int cl = 0; cl < 4; cl++) {
                if (cl >= r - 8 && cl <= r) {
                    const float wv = c_w[(cb + cl) * Ss + (r - cl)];
                    acc[cl].x = fmaf(wv, tp.x, acc[cl].x);
                    acc[cl].y = fmaf(wv, tp.y, acc[cl].y);
                    acc[cl].z = fmaf(wv, tp.z, acc[cl].z);
                    acc[cl].w = fmaf(wv, tp.w, acc[cl].w);
                }
            }
        }
    }
}

// ---- Pass A: conv + stats, no output write.
__global__ __launch_bounds__(256, 5) void stats_kernel(const float* __restrict__ x)
{
    const int lane = threadIdx.x & 31;
    const int wid  = threadIdx.x >> 5;
    const int tb   = blockIdx.x * TBLK + lane * 4;
    const int cb   = blockIdx.y * CG + wid * 4;
    const int n    = blockIdx.z;
    const float* xn = x + (size_t)n * Cc * Tt;

    float4 acc[4];
    #pragma unroll
    for (int cl = 0; cl < 4; cl++) acc[cl] = make_float4(0.f, 0.f, 0.f, 0.f);

    const bool edge = (blockIdx.x == 0) || (blockIdx.x == Tt / TBLK - 1);
    if (edge) conv_quad<true >(xn, cb, tb, acc);
    else      conv_quad<false>(xn, cb, tb, acc);

    #pragma unroll
    for (int cl = 0; cl < 4; cl++) {
        const float4 a = acc[cl];
        float s1 = (a.x + a.y) + (a.z + a.w);
        float s2 = fmaf(a.x, a.x, fmaf(a.y, a.y, fmaf(a.z, a.z, a.w * a.w)));
        #pragma unroll
        for (int o = 16; o > 0; o >>= 1) {
            s1 += __shfl_down_sync(0xffffffffu, s1, o);
            s2 += __shfl_down_sync(0xffffffffu, s2, o);
        }
        if (lane == 0) {
            atomicAdd(&g_sum[cb + cl],   s1);
            atomicAdd(&g_sumsq[cb + cl], s2);
        }
    }
}

// ---- Finalize: per-channel scale/bias.
__global__ void finalize_kernel(const float* __restrict__ gamma,
                                const float* __restrict__ beta)
{
    int c = threadIdx.x;
    if (c >= Cc) return;
    const float inv = 1.0f / ((float)Nn * (float)Tt);
    float mean = g_sum[c] * inv;
    float var  = g_sumsq[c] * inv - mean * mean;
    float rstd = rsqrtf(var + 1e-5f);
    float sc   = gamma[c] * rstd;
    g_scale[c] = sc;
    g_bias[c]  = beta[c] - mean * sc;
}

// ---- Pass B: conv again + normalize + relu + store.
__global__ __launch_bounds__(256, 5) void conv_out_kernel(
    const float* __restrict__ x, float* __restrict__ out)
{
    const int lane = threadIdx.x & 31;
    const int wid  = threadIdx.x >> 5;
    const int tb   = blockIdx.x * TBLK + lane * 4;
    const int cb   = blockIdx.y * CG + wid * 4;
    const int n    = blockIdx.z;
    const float* xn = x + (size_t)n * Cc * Tt;

    float4 acc[4];
    #pragma unroll
    for (int cl = 0; cl < 4; cl++) acc[cl] = make_float4(0.f, 0.f, 0.f, 0.f);

    const bool edge = (blockIdx.x == 0) || (blockIdx.x == Tt / TBLK - 1);
    if (edge) conv_quad<true >(xn, cb, tb, acc);
    else      conv_quad<false>(xn, cb, tb, acc);

    #pragma unroll
    for (int cl = 0; cl < 4; cl++) {
        const int c = cb + cl;
        const float sc = g_scale[c];
        const float bs = g_bias[c];
        float4 a = acc[cl];
        a.x = fmaxf(fmaf(a.x, sc, bs), 0.0f);
        a.y = fmaxf(fmaf(a.y, sc, bs), 0.0f);
        a.z = fmaxf(fmaf(a.z, sc, bs), 0.0f);
        a.w = fmaxf(fmaf(a.w, sc, bs), 0.0f);
        *reinterpret_cast<float4*>(out + ((size_t)n * Cc + c) * Tt + tb) = a;
    }
}

extern "C" void kernel_launch(void* const* d_in, const int* in_sizes, int n_in,
                              void* d_out, int out_size)
{
    const float* x     = (const float*)d_in[0];
    const float* w     = (const float*)d_in[1];
    const float* gamma = (const float*)d_in[2];
    const float* beta  = (const float*)d_in[3];
    float* out = (float*)d_out;

    // Weights into constant memory (device-to-device, graph-capturable).
    cudaMemcpyToSymbolAsync(c_w, w, Cc * Ss * sizeof(float), 0,
                            cudaMemcpyDeviceToDevice, 0);

    const dim3 grid(Tt / TBLK, Cc / CG, Nn);   // 16 x 4 x 64 = 4096 blocks
    init_kernel<<<1, 128>>>();
    stats_kernel<<<grid, 256>>>(x);
    finalize_kernel<<<1, 128>>>(gamma, beta);
    conv_out_kernel<<<grid, 256>>>(x, out);
}

// round 12
// speedup vs baseline: 1.3311x; 1.3311x over previous
#include <cuda_runtime.h>

// S2Conv v6b: no-smem streaming conv with lane-contiguous (coalesced) scalar
// loads. Warp tile = 4 channels x 128 t as 4 segments of 32 consecutive t
// (lane = position in segment) -> every tap load is a coalesced LDG.32
// regardless of the per-row t-shift. Recompute strategy: Pass A = conv+stats;
// finalize; Pass B = conv again + scale/bias + relu + store.
// N=64, C=128, T=2048, S=9.

#define Nn 64
#define Cc 128
#define Tt 2048
#define Ss 9
#define CG 32          // output channels per block (8 warps x 4)
#define TBLK 128       // t per warp (4 segments x 32)

__device__ float g_sum[Cc];
__device__ float g_sumsq[Cc];
__device__ float g_scale[Cc];
__device__ float g_bias[Cc];
__constant__ float c_w[Cc * Ss];

__global__ void init_kernel() {
    int i = threadIdx.x;
    if (i < Cc) { g_sum[i] = 0.0f; g_sumsq[i] = 0.0f; }
}

// Core conv: acc[cl][s] += w[cb+cl, r-cl] * xs[cb-4+r, tbase + 32s]
// where tbase already contains this thread's lane. xs[cc,t] = x[cc, t+4-cc%9],
// zero-padded outside [0,Tt).
template<bool EDGE>
__device__ __forceinline__ void conv_core(
    const float* __restrict__ xn, int cb, int tbase, float (&acc)[4][4])
{
    #pragma unroll
    for (int r = 0; r < 12; r++) {
        const int cc = cb - 4 + r;
        if ((unsigned)cc < (unsigned)Cc) {          // warp-uniform
            const int off = 4 - (cc % 9);
            const float* xr = xn + (size_t)cc * Tt + tbase + off;
            float v[4];
            #pragma unroll
            for (int s = 0; s < 4; s++) {
                if (EDGE) {
                    const int ts = tbase + s * 32 + off;   // per-lane global t
                    v[s] = ((unsigned)ts < (unsigned)Tt) ? __ldg(&xr[s * 32]) : 0.f;
                } else {
                    v[s] = __ldg(&xr[s * 32]);
                }
            }
            #pragma unroll
            for (int cl = 0; cl < 4; cl++) {
                if (cl >= r - 8 && cl <= r) {
                    const float wv = c_w[(cb + cl) * Ss + (r - cl)];
                    #pragma unroll
                    for (int s = 0; s < 4; s++)
                        acc[cl][s] = fmaf(wv, v[s], acc[cl][s]);
                }
            }
        }
    }
}

// ---- Pass A: conv + per-channel stats, no output write.
__global__ __launch_bounds__(256, 6) void stats_kernel(const float* __restrict__ x)
{
    const int lane = threadIdx.x & 31;
    const int wid  = threadIdx.x >> 5;
    const int cb   = blockIdx.y * CG + wid * 4;
    const int n    = blockIdx.z;
    const int tbase = blockIdx.x * TBLK + lane;     // lane folded into base
    const float* xn = x + (size_t)n * Cc * Tt;

    float acc[4][4];
    #pragma unroll
    for (int cl = 0; cl < 4; cl++)
        #pragma unroll
        for (int s = 0; s < 4; s++) acc[cl][s] = 0.f;

    const bool edge = (blockIdx.x == 0) || (blockIdx.x == Tt / TBLK - 1);
    if (edge) conv_core<true >(xn, cb, tbase, acc);
    else      conv_core<false>(xn, cb, tbase, acc);

    #pragma unroll
    for (int cl = 0; cl < 4; cl++) {
        float s1 = (acc[cl][0] + acc[cl][1]) + (acc[cl][2] + acc[cl][3]);
        float s2 = fmaf(acc[cl][0], acc[cl][0], fmaf(acc[cl][1], acc[cl][1],
                   fmaf(acc[cl][2], acc[cl][2], acc[cl][3] * acc[cl][3])));
        #pragma unroll
        for (int o = 16; o > 0; o >>= 1) {
            s1 += __shfl_down_sync(0xffffffffu, s1, o);
            s2 += __shfl_down_sync(0xffffffffu, s2, o);
        }
        if (lane == 0) {
            atomicAdd(&g_sum[cb + cl],   s1);
            atomicAdd(&g_sumsq[cb + cl], s2);
        }
    }
}

// ---- Finalize: per-channel scale/bias.
__global__ void finalize_kernel(const float* __restrict__ gamma,
                                const float* __restrict__ beta)
{
    int c = threadIdx.x;
    if (c >= Cc) return;
    const float inv = 1.0f / ((float)Nn * (float)Tt);
    float mean = g_sum[c] * inv;
    float var  = g_sumsq[c] * inv - mean * mean;
    float rstd = rsqrtf(var + 1e-5f);
    float sc   = gamma[c] * rstd;
    g_scale[c] = sc;
    g_bias[c]  = beta[c] - mean * sc;
}

// ---- Pass B: conv again + normalize + relu + store (coalesced scalar STG).
__global__ __launch_bounds__(256, 6) void conv_out_kernel(
    const float* __restrict__ x, float* __restrict__ out)
{
    const int lane = threadIdx.x & 31;
    const int wid  = threadIdx.x >> 5;
    const int cb   = blockIdx.y * CG + wid * 4;
    const int n    = blockIdx.z;
    const int tbase = blockIdx.x * TBLK + lane;
    const float* xn = x + (size_t)n * Cc * Tt;

    float acc[4][4];
    #pragma unroll
    for (int cl = 0; cl < 4; cl++)
        #pragma unroll
        for (int s = 0; s < 4; s++) acc[cl][s] = 0.f;

    const bool edge = (blockIdx.x == 0) || (blockIdx.x == Tt / TBLK - 1);
    if (edge) conv_core<true >(xn, cb, tbase, acc);
    else      conv_core<false>(xn, cb, tbase, acc);

    #pragma unroll
    for (int cl = 0; cl < 4; cl++) {
        const int c = cb + cl;
        const float sc = g_scale[c];
        const float bs = g_bias[c];
        float* orow = out + ((size_t)n * Cc + c) * Tt + tbase;
        #pragma unroll
        for (int s = 0; s < 4; s++)
            orow[s * 32] = fmaxf(fmaf(acc[cl][s], sc, bs), 0.0f);
    }
}

extern "C" void kernel_launch(void* const* d_in, const int* in_sizes, int n_in,
                              void* d_out, int out_size)
{
    const float* x     = (const float*)d_in[0];
    const float* w     = (const float*)d_in[1];
    const float* gamma = (const float*)d_in[2];
    const float* beta  = (const float*)d_in[3];
    float* out = (float*)d_out;

    cudaMemcpyToSymbolAsync(c_w, w, Cc * Ss * sizeof(float), 0,
                            cudaMemcpyDeviceToDevice, 0);

    const dim3 grid(Tt / TBLK, Cc / CG, Nn);   // 16 x 4 x 64 = 4096 blocks
    init_kernel<<<1, 128>>>();
    stats_kernel<<<grid, 256>>>(x);
    finalize_kernel<<<1, 128>>>(gamma, beta);
    conv_out_kernel<<<grid, 256>>>(x, out);
}

// round 14
// speedup vs baseline: 1.7156x; 1.2888x over previous
#include <cuda_runtime.h>

// S2Conv v7: branchless, load-batched streaming conv (no smem).
// Warp tile = 4 channels x 128 t (4 segments of 32 consecutive t, lane = pos).
// Rows loaded in waves of 4 (16 batched LDGs) -> high MLP, no per-row branches:
// row/t validity handled by SEL on the loaded value (clamped addresses).
// Recompute strategy: Pass A = conv + stats; finalize; Pass B = conv + norm + store.
// N=64, C=128, T=2048, S=9.

#define Nn 64
#define Cc 128
#define Tt 2048
#define Ss 9
#define CG 32          // output channels per block (8 warps x 4)
#define TBLK 128       // t per warp (4 segments x 32)

__device__ float g_sum[Cc];
__device__ float g_sumsq[Cc];
__device__ float g_scale[Cc];
__device__ float g_bias[Cc];
__constant__ float c_w[Cc * Ss];

__global__ void init_kernel() {
    int i = threadIdx.x;
    if (i < Cc) { g_sum[i] = 0.0f; g_sumsq[i] = 0.0f; }
}

// acc[cl][s] += w[cb+cl, r-cl] * xs[cb-4+r, tbase + 32s], r = 0..11.
// tbase includes this thread's lane. xs[cc,t] = x[cc, t+4-cc%9], zero-padded.
// CEDGE: block may touch cc outside [0,Cc) -> SEL-zero (clamped address).
// TEDGE: block may touch t outside [0,Tt) -> SEL-zero (clamped address).
template<bool CEDGE, bool TEDGE>
__device__ __forceinline__ void conv_core(
    const float* __restrict__ xn, int cb, int tbase, float (&acc)[4][4])
{
    #pragma unroll
    for (int wv = 0; wv < 3; wv++) {               // 3 waves of 4 rows
        float v[4][4];
        // ---- batched loads: 16 LDGs, no branches
        #pragma unroll
        for (int i = 0; i < 4; i++) {
            const int r  = wv * 4 + i;
            const int cc = cb - 4 + r;
            const int ccl = CEDGE ? min(max(cc, 0), Cc - 1) : cc;
            const int off = 4 - (ccl % 9);
            const float* xr = xn + (size_t)ccl * Tt + tbase + off;
            #pragma unroll
            for (int s = 0; s < 4; s++) {
                float t;
                if (TEDGE) {
                    const int ts  = tbase + s * 32 + off;      // per-lane global t
                    const int tsc = min(max(ts, 0), Tt - 1);
                    t = __ldg(xn + (size_t)ccl * Tt + tsc);
                    t = ((unsigned)ts < (unsigned)Tt) ? t : 0.0f;
                } else {
                    t = __ldg(&xr[s * 32]);
                }
                if (CEDGE) t = ((unsigned)cc < (unsigned)Cc) ? t : 0.0f;
                v[i][s] = t;
            }
        }
        // ---- FMAs on the wave
        #pragma unroll
        for (int i = 0; i < 4; i++) {
            const int r = wv * 4 + i;
            #pragma unroll
            for (int cl = 0; cl < 4; cl++) {
                if (cl >= r - 8 && cl <= r) {
                    const float wt = c_w[(cb + cl) * Ss + (r - cl)];   // warp-uniform
                    #pragma unroll
                    for (int s = 0; s < 4; s++)
                        acc[cl][s] = fmaf(wt, v[i][s], acc[cl][s]);
                }
            }
        }
    }
}

// ---- Pass A: conv + per-channel stats, no output write.
__global__ __launch_bounds__(256, 4) void stats_kernel(const float* __restrict__ x)
{
    const int lane = threadIdx.x & 31;
    const int wid  = threadIdx.x >> 5;
    const int cb   = blockIdx.y * CG + wid * 4;
    const int n    = blockIdx.z;
    const int tbase = blockIdx.x * TBLK + lane;
    const float* xn = x + (size_t)n * Cc * Tt;

    float acc[4][4];
    #pragma unroll
    for (int cl = 0; cl < 4; cl++)
        #pragma unroll
        for (int s = 0; s < 4; s++) acc[cl][s] = 0.f;

    const bool tedge = (blockIdx.x == 0) || (blockIdx.x == Tt / TBLK - 1);
    const bool cedge = (blockIdx.y == 0) || (blockIdx.y == Cc / CG - 1);
    if      ( cedge &&  tedge) conv_core<true , true >(xn, cb, tbase, acc);
    else if ( cedge && !tedge) conv_core<true , false>(xn, cb, tbase, acc);
    else if (!cedge &&  tedge) conv_core<false, true >(xn, cb, tbase, acc);
    else                       conv_core<false, false>(xn, cb, tbase, acc);

    #pragma unroll
    for (int cl = 0; cl < 4; cl++) {
        float s1 = (acc[cl][0] + acc[cl][1]) + (acc[cl][2] + acc[cl][3]);
        float s2 = fmaf(acc[cl][0], acc[cl][0], fmaf(acc[cl][1], acc[cl][1],
                   fmaf(acc[cl][2], acc[cl][2], acc[cl][3] * acc[cl][3])));
        #pragma unroll
        for (int o = 16; o > 0; o >>= 1) {
            s1 += __shfl_down_sync(0xffffffffu, s1, o);
            s2 += __shfl_down_sync(0xffffffffu, s2, o);
        }
        if (lane == 0) {
            atomicAdd(&g_sum[cb + cl],   s1);
            atomicAdd(&g_sumsq[cb + cl], s2);
        }
    }
}

// ---- Finalize: per-channel scale/bias.
__global__ void finalize_kernel(const float* __restrict__ gamma,
                                const float* __restrict__ beta)
{
    int c = threadIdx.x;
    if (c >= Cc) return;
    const float inv = 1.0f / ((float)Nn * (float)Tt);
    float mean = g_sum[c] * inv;
    float var  = g_sumsq[c] * inv - mean * mean;
    float rstd = rsqrtf(var + 1e-5f);
    float sc   = gamma[c] * rstd;
    g_scale[c] = sc;
    g_bias[c]  = beta[c] - mean * sc;
}

// ---- Pass B: conv again + normalize + relu + store (coalesced scalar STG).
__global__ __launch_bounds__(256, 4) void conv_out_kernel(
    const float* __restrict__ x, float* __restrict__ out)
{
    const int lane = threadIdx.x & 31;
    const int wid  = threadIdx.x >> 5;
    const int cb   = blockIdx.y * CG + wid * 4;
    const int n    = blockIdx.z;
    const int tbase = blockIdx.x * TBLK + lane;
    const float* xn = x + (size_t)n * Cc * Tt;

    float acc[4][4];
    #pragma unroll
    for (int cl = 0; cl < 4; cl++)
        #pragma unroll
        for (int s = 0; s < 4; s++) acc[cl][s] = 0.f;

    const bool tedge = (blockIdx.x == 0) || (blockIdx.x == Tt / TBLK - 1);
    const bool cedge = (blockIdx.y == 0) || (blockIdx.y == Cc / CG - 1);
    if      ( cedge &&  tedge) conv_core<true , true >(xn, cb, tbase, acc);
    else if ( cedge && !tedge) conv_core<true , false>(xn, cb, tbase, acc);
    else if (!cedge &&  tedge) conv_core<false, true >(xn, cb, tbase, acc);
    else                       conv_core<false, false>(xn, cb, tbase, acc);

    #pragma unroll
    for (int cl = 0; cl < 4; cl++) {
        const int c = cb + cl;
        const float sc = g_scale[c];
        const float bs = g_bias[c];
        float* orow = out + ((size_t)n * Cc + c) * Tt + tbase;
        #pragma unroll
        for (int s = 0; s < 4; s++)
            orow[s * 32] = fmaxf(fmaf(acc[cl][s], sc, bs), 0.0f);
    }
}

extern "C" void kernel_launch(void* const* d_in, const int* in_sizes, int n_in,
                              void* d_out, int out_size)
{
    const float* x     = (const float*)d_in[0];
    const float* w     = (const float*)d_in[1];
    const float* gamma = (const float*)d_in[2];
    const float* beta  = (const float*)d_in[3];
    float* out = (float*)d_out;

    cudaMemcpyToSymbolAsync(c_w, w, Cc * Ss * sizeof(float), 0,
                            cudaMemcpyDeviceToDevice, 0);

    const dim3 grid(Tt / TBLK, Cc / CG, Nn);   // 16 x 4 x 64 = 4096 blocks
    init_kernel<<<1, 128>>>();
    stats_kernel<<<grid, 256>>>(x);
    finalize_kernel<<<1, 128>>>(gamma, beta);
    conv_out_kernel<<<grid, 256>>>(x, out);
}

// round 15
// speedup vs baseline: 1.9277x; 1.1236x over previous
#include <cuda_runtime.h>

// S2Conv v8: single conv pass (v7 branchless/batched core) that stores the
// raw conv output AND accumulates per-channel stats; finalize; then a light
// normalize+relu pass over the (L2-resident) output.
// N=64, C=128, T=2048, S=9.

#define Nn 64
#define Cc 128
#define Tt 2048
#define Ss 9
#define CG 32          // output channels per block (8 warps x 4)
#define TBLK 128       // t per warp (4 segments x 32)

__device__ float g_sum[Cc];
__device__ float g_sumsq[Cc];
__device__ float g_scale[Cc];
__device__ float g_bias[Cc];
__constant__ float c_w[Cc * Ss];

__global__ void init_kernel() {
    int i = threadIdx.x;
    if (i < Cc) { g_sum[i] = 0.0f; g_sumsq[i] = 0.0f; }
}

// acc[cl][s] += w[cb+cl, r-cl] * xs[cb-4+r, tbase + 32s], r = 0..11.
// tbase includes this thread's lane. xs[cc,t] = x[cc, t+4-cc%9], zero-padded.
// CEDGE / TEDGE: clamp+SEL instead of branches.
template<bool CEDGE, bool TEDGE>
__device__ __forceinline__ void conv_core(
    const float* __restrict__ xn, int cb, int tbase, float (&acc)[4][4])
{
    #pragma unroll
    for (int wv = 0; wv < 3; wv++) {               // 3 waves of 4 rows
        float v[4][4];
        // ---- batched loads: 16 LDGs, no branches
        #pragma unroll
        for (int i = 0; i < 4; i++) {
            const int r  = wv * 4 + i;
            const int cc = cb - 4 + r;
            const int ccl = CEDGE ? min(max(cc, 0), Cc - 1) : cc;
            const int off = 4 - (ccl % 9);
            const float* xr = xn + (size_t)ccl * Tt + tbase + off;
            #pragma unroll
            for (int s = 0; s < 4; s++) {
                float t;
                if (TEDGE) {
                    const int ts  = tbase + s * 32 + off;      // per-lane global t
                    const int tsc = min(max(ts, 0), Tt - 1);
                    t = __ldg(xn + (size_t)ccl * Tt + tsc);
                    t = ((unsigned)ts < (unsigned)Tt) ? t : 0.0f;
                } else {
                    t = __ldg(&xr[s * 32]);
                }
                if (CEDGE) t = ((unsigned)cc < (unsigned)Cc) ? t : 0.0f;
                v[i][s] = t;
            }
        }
        // ---- FMAs on the wave
        #pragma unroll
        for (int i = 0; i < 4; i++) {
            const int r = wv * 4 + i;
            #pragma unroll
            for (int cl = 0; cl < 4; cl++) {
                if (cl >= r - 8 && cl <= r) {
                    const float wt = c_w[(cb + cl) * Ss + (r - cl)];   // warp-uniform
                    #pragma unroll
                    for (int s = 0; s < 4; s++)
                        acc[cl][s] = fmaf(wt, v[i][s], acc[cl][s]);
                }
            }
        }
    }
}

// ---- Pass 1: conv + store raw + per-channel stats.
__global__ __launch_bounds__(256, 4) void conv_stats_kernel(
    const float* __restrict__ x, float* __restrict__ out)
{
    const int lane = threadIdx.x & 31;
    const int wid  = threadIdx.x >> 5;
    const int cb   = blockIdx.y * CG + wid * 4;
    const int n    = blockIdx.z;
    const int tbase = blockIdx.x * TBLK + lane;     // lane folded in
    const float* xn = x + (size_t)n * Cc * Tt;

    float acc[4][4];
    #pragma unroll
    for (int cl = 0; cl < 4; cl++)
        #pragma unroll
        for (int s = 0; s < 4; s++) acc[cl][s] = 0.f;

    const bool tedge = (blockIdx.x == 0) || (blockIdx.x == Tt / TBLK - 1);
    const bool cedge = (blockIdx.y == 0) || (blockIdx.y == Cc / CG - 1);
    if      ( cedge &&  tedge) conv_core<true , true >(xn, cb, tbase, acc);
    else if ( cedge && !tedge) conv_core<true , false>(xn, cb, tbase, acc);
    else if (!cedge &&  tedge) conv_core<false, true >(xn, cb, tbase, acc);
    else                       conv_core<false, false>(xn, cb, tbase, acc);

    // Store raw conv output (coalesced scalar STG).
    #pragma unroll
    for (int cl = 0; cl < 4; cl++) {
        float* orow = out + ((size_t)n * Cc + cb + cl) * Tt + tbase;
        #pragma unroll
        for (int s = 0; s < 4; s++)
            orow[s * 32] = acc[cl][s];
    }

    // Per-channel stats: local -> warp shuffle -> global atomic.
    #pragma unroll
    for (int cl = 0; cl < 4; cl++) {
        float s1 = (acc[cl][0] + acc[cl][1]) + (acc[cl][2] + acc[cl][3]);
        float s2 = fmaf(acc[cl][0], acc[cl][0], fmaf(acc[cl][1], acc[cl][1],
                   fmaf(acc[cl][2], acc[cl][2], acc[cl][3] * acc[cl][3])));
        #pragma unroll
        for (int o = 16; o > 0; o >>= 1) {
            s1 += __shfl_down_sync(0xffffffffu, s1, o);
            s2 += __shfl_down_sync(0xffffffffu, s2, o);
        }
        if (lane == 0) {
            atomicAdd(&g_sum[cb + cl],   s1);
            atomicAdd(&g_sumsq[cb + cl], s2);
        }
    }
}

// ---- Finalize: per-channel scale/bias.
__global__ void finalize_kernel(const float* __restrict__ gamma,
                                const float* __restrict__ beta)
{
    int c = threadIdx.x;
    if (c >= Cc) return;
    const float inv = 1.0f / ((float)Nn * (float)Tt);
    float mean = g_sum[c] * inv;
    float var  = g_sumsq[c] * inv - mean * mean;
    float rstd = rsqrtf(var + 1e-5f);
    float sc   = gamma[c] * rstd;
    g_scale[c] = sc;
    g_bias[c]  = beta[c] - mean * sc;
}

// ---- Pass 3: in-place normalize + relu (out is L2-resident). One block/row.
__global__ __launch_bounds__(256) void norm_kernel(float* __restrict__ out)
{
    const int row = blockIdx.x;          // n*C + c
    const int c   = row & (Cc - 1);
    const float sc = g_scale[c];
    const float b  = g_bias[c];
    float4* p = reinterpret_cast<float4*>(out + (size_t)row * Tt);
    const int tid = threadIdx.x;
    #pragma unroll
    for (int k = 0; k < (Tt / 4) / 256; k++) {
        float4 v = p[tid + k * 256];
        v.x = fmaxf(fmaf(v.x, sc, b), 0.0f);
        v.y = fmaxf(fmaf(v.y, sc, b), 0.0f);
        v.z = fmaxf(fmaf(v.z, sc, b), 0.0f);
        v.w = fmaxf(fmaf(v.w, sc, b), 0.0f);
        p[tid + k * 256] = v;
    }
}

extern "C" void kernel_launch(void* const* d_in, const int* in_sizes, int n_in,
                              void* d_out, int out_size)
{
    const float* x     = (const float*)d_in[0];
    const float* w     = (const float*)d_in[1];
    const float* gamma = (const float*)d_in[2];
    const float* beta  = (const float*)d_in[3];
    float* out = (float*)d_out;

    cudaMemcpyToSymbolAsync(c_w, w, Cc * Ss * sizeof(float), 0,
                            cudaMemcpyDeviceToDevice, 0);

    const dim3 grid(Tt / TBLK, Cc / CG, Nn);   // 16 x 4 x 64 = 4096 blocks
    init_kernel<<<1, 128>>>();
    conv_stats_kernel<<<grid, 256>>>(x, out);
    finalize_kernel<<<1, 128>>>(gamma, beta);
    norm_kernel<<<Nn * Cc, 256>>>(out);
}